// round 5
// baseline (speedup 1.0000x reference)
#include <cuda_runtime.h>
#include <cuda_bf16.h>
#include <math.h>
#include <stdint.h>

#define SQB 16384
#define SKK 4096
#define DDK 512
#define DVV 256

__device__ __align__(256) float g_K[SKK * DDK];
__device__ __align__(256) float g_V[SKK * DVV];
__device__ __align__(256) float g_S[(long long)SQB * SKK];
__device__ __align__(256) __nv_bfloat16 g_Xh[(long long)SQB * DDK];
__device__ __align__(256) __nv_bfloat16 g_Xl[(long long)SQB * DDK];
__device__ __align__(256) __nv_bfloat16 g_Kh[SKK * DDK];
__device__ __align__(256) __nv_bfloat16 g_Kl[SKK * DDK];
__device__ __align__(256) __nv_bfloat16 g_Vth[DVV * SKK];
__device__ __align__(256) __nv_bfloat16 g_Vtl[DVV * SKK];
__device__ __align__(256) __nv_bfloat16 g_Ph[(long long)SQB * SKK];
__device__ __align__(256) __nv_bfloat16 g_Pl[(long long)SQB * SKK];

// ---------------- helpers ----------------
__device__ __forceinline__ uint32_t smem_u32(const void* p) {
    uint32_t a;
    asm("{ .reg .u64 t; cvta.to.shared.u64 t, %1; cvt.u32.u64 %0, t; }" : "=r"(a) : "l"(p));
    return a;
}
__device__ __forceinline__ void cp16(uint32_t s, const __nv_bfloat16* g) {
    asm volatile("cp.async.cg.shared.global [%0], [%1], 16;"
                 :: "r"(s), "l"(__cvta_generic_to_global(g)) : "memory");
}
#define CP_COMMIT() asm volatile("cp.async.commit_group;" ::: "memory")
#define CP_WAIT(n)  asm volatile("cp.async.wait_group %0;" :: "n"(n) : "memory")

#define LDSM4(r, a) \
    asm volatile("ldmatrix.sync.aligned.m8n8.x4.shared.b16 {%0,%1,%2,%3}, [%4];" \
                 : "=r"((r)[0]), "=r"((r)[1]), "=r"((r)[2]), "=r"((r)[3]) : "r"(a))

#define MMA_BF16(d, a, b) \
    asm volatile("mma.sync.aligned.m16n8k16.row.col.f32.bf16.bf16.f32 " \
                 "{%0,%1,%2,%3}, {%4,%5,%6,%7}, {%8,%9}, {%0,%1,%2,%3};" \
                 : "+f"((d)[0]), "+f"((d)[1]), "+f"((d)[2]), "+f"((d)[3]) \
                 : "r"((a)[0]), "r"((a)[1]), "r"((a)[2]), "r"((a)[3]), \
                   "r"((b)[0]), "r"((b)[1]))

// ---------------- HMMA NT GEMM with bf16 hi/lo 3-MMA split ----------------
// C[M,N] = (Ah+Al)[M,K] * (Bh+Bl)[N,K]^T * scale   (dropping Al*Bl)
// CTA: 128x128 tile, 256 threads (8 warps, each 64x32).
// K-chunk 32, 3-stage cp.async pipeline, ONE __syncthreads per chunk.
#define KC 32
#define ROWB 80                 // 64B data + 16B pad per smem row
#define PLANE (128 * ROWB)      // 10240 B
#define OFF_AH 0
#define OFF_AL (1 * PLANE)
#define OFF_BH (2 * PLANE)
#define OFF_BL (3 * PLANE)
#define STAGE  (4 * PLANE)      // 40960 B
#define NSTG   3
#define SMEMSZ (NSTG * STAGE)   // 122880 B

__device__ __forceinline__ void load_stage(
    uint32_t base, int tid, int kc0, int Kdim,
    const __nv_bfloat16* __restrict__ Ah, const __nv_bfloat16* __restrict__ Al,
    const __nv_bfloat16* __restrict__ Bh, const __nv_bfloat16* __restrict__ Bl,
    long long m0, long long n0)
{
#pragma unroll
    for (int it = 0; it < 2; it++) {
        const int j = tid + it * 256;        // 512 jobs: 128 rows x 4 parts
        const int row = j >> 2;
        const int part = j & 3;
        const uint32_t off = (uint32_t)row * ROWB + part * 16;
        const long long ga = (m0 + row) * (long long)Kdim + kc0 + part * 8;
        const long long gb = (n0 + row) * (long long)Kdim + kc0 + part * 8;
        cp16(base + OFF_AH + off, Ah + ga);
        cp16(base + OFF_AL + off, Al + ga);
        cp16(base + OFF_BH + off, Bh + gb);
        cp16(base + OFF_BL + off, Bl + gb);
    }
    CP_COMMIT();
}

__global__ __launch_bounds__(256)
void hmma_gemm_nt(const __nv_bfloat16* __restrict__ Ah, const __nv_bfloat16* __restrict__ Al,
                  const __nv_bfloat16* __restrict__ Bh, const __nv_bfloat16* __restrict__ Bl,
                  float* __restrict__ C, int Kdim, int ldc, float scale)
{
    extern __shared__ char sm[];
    const uint32_t sb = smem_u32(sm);

    const int tid  = threadIdx.x;
    const int lane = tid & 31;
    const int wid  = tid >> 5;
    const int wm   = wid & 1;    // 2 warps along M
    const int wn   = wid >> 1;   // 4 warps along N
    const long long m0 = (long long)blockIdx.y * 128;
    const long long n0 = (long long)blockIdx.x * 128;

    float acc[4][4][4];
#pragma unroll
    for (int i = 0; i < 4; i++)
#pragma unroll
        for (int j = 0; j < 4; j++)
#pragma unroll
            for (int k = 0; k < 4; k++) acc[i][j][k] = 0.f;

    const int NC = Kdim / KC;

    // prologue: stages 0,1 <- chunks 0,1
    load_stage(sb,         tid, 0,  Kdim, Ah, Al, Bh, Bl, m0, n0);
    load_stage(sb + STAGE, tid, KC, Kdim, Ah, Al, Bh, Bl, m0, n0);

    const int g = lane >> 3;
    const int r = lane & 7;

    int st_c = 0;   // stage holding chunk c
    int st_l = 2;   // stage targeted by the load issued this iteration (chunk c+2)

    for (int c = 0; c < NC; c++) {
        // chunk c complete (chunk c+1 may still be in flight)
        if (c + 1 < NC) { CP_WAIT(1); } else { CP_WAIT(0); }
        __syncthreads();   // visibility of chunk c; stage st_l free (read in iter c-1)

        // prefetch chunk c+2 into st_l, overlapping with compute below
        if (c + 2 < NC)
            load_stage(sb + st_l * STAGE, tid, (c + 2) * KC, Kdim, Ah, Al, Bh, Bl, m0, n0);

        const uint32_t base = sb + st_c * STAGE;
#pragma unroll
        for (int ks = 0; ks < 2; ks++) {
            uint32_t a_h[4][4], a_l[4][4], b_h[4][2], b_l[4][2];
#pragma unroll
            for (int mi = 0; mi < 4; mi++) {
                const uint32_t row = wm * 64 + mi * 16 + (g & 1) * 8 + r;
                const uint32_t cb  = ks * 32 + (g >> 1) * 16;
                const uint32_t ad  = base + OFF_AH + row * ROWB + cb;
                LDSM4(a_h[mi], ad);
                LDSM4(a_l[mi], ad + (OFF_AL - OFF_AH));
            }
#pragma unroll
            for (int np = 0; np < 2; np++) {
                const uint32_t row = wn * 32 + np * 16 + (g >> 1) * 8 + r;
                const uint32_t cb  = ks * 32 + (g & 1) * 16;
                const uint32_t bd  = base + OFF_BH + row * ROWB + cb;
                uint32_t t[4];
                LDSM4(t, bd);
                b_h[np * 2][0] = t[0]; b_h[np * 2][1] = t[1];
                b_h[np * 2 + 1][0] = t[2]; b_h[np * 2 + 1][1] = t[3];
                LDSM4(t, bd + (OFF_BL - OFF_BH));
                b_l[np * 2][0] = t[0]; b_l[np * 2][1] = t[1];
                b_l[np * 2 + 1][0] = t[2]; b_l[np * 2 + 1][1] = t[3];
            }
#pragma unroll
            for (int mi = 0; mi < 4; mi++)
#pragma unroll
                for (int ni = 0; ni < 4; ni++) {
                    MMA_BF16(acc[mi][ni], a_h[mi], b_h[ni]);
                    MMA_BF16(acc[mi][ni], a_h[mi], b_l[ni]);
                    MMA_BF16(acc[mi][ni], a_l[mi], b_h[ni]);
                }
        }
        st_c = (st_c == NSTG - 1) ? 0 : st_c + 1;
        st_l = (st_l == NSTG - 1) ? 0 : st_l + 1;
    }

    // epilogue: fragment -> gmem (float2 stores)
#pragma unroll
    for (int mi = 0; mi < 4; mi++)
#pragma unroll
        for (int ni = 0; ni < 4; ni++) {
            const long long row = m0 + wm * 64 + mi * 16 + (lane >> 2);
            const long long col = n0 + wn * 32 + ni * 8 + 2 * (lane & 3);
            float2 v0 = make_float2(acc[mi][ni][0] * scale, acc[mi][ni][1] * scale);
            float2 v1 = make_float2(acc[mi][ni][2] * scale, acc[mi][ni][3] * scale);
            *(float2*)&C[row * ldc + col]       = v0;
            *(float2*)&C[(row + 8) * ldc + col] = v1;
        }
}

// ---------------- fp32 NT SGEMM for projections ----------------
#define BM 128
#define BN 128
#define BKK 8
#define PADW 132

__global__ __launch_bounds__(256, 2)
void sgemm_nt(const float* __restrict__ Ag, const float* __restrict__ Bg,
              float* __restrict__ Cg, int N, int K)
{
    __shared__ float As[2][BKK][PADW];
    __shared__ float Bs[2][BKK][PADW];

    const int tid = threadIdx.x;
    const int tx = tid & 15, ty = tid >> 4;
    const int row0 = blockIdx.y * BM, col0 = blockIdx.x * BN;
    const int aRow = row0 + (tid >> 1);
    const int aCol = (tid & 1) * 4;
    const int bRow = col0 + (tid >> 1);

    float acc[8][8];
#pragma unroll
    for (int i = 0; i < 8; i++)
#pragma unroll
        for (int j = 0; j < 8; j++) acc[i][j] = 0.f;

    const int nt = K / BKK;
    float4 ra = *(const float4*)&Ag[(long long)aRow * K + aCol];
    float4 rb = *(const float4*)&Bg[(long long)bRow * K + aCol];
    {
        const int m = tid >> 1;
        As[0][aCol + 0][m] = ra.x; As[0][aCol + 1][m] = ra.y;
        As[0][aCol + 2][m] = ra.z; As[0][aCol + 3][m] = ra.w;
        Bs[0][aCol + 0][m] = rb.x; Bs[0][aCol + 1][m] = rb.y;
        Bs[0][aCol + 2][m] = rb.z; Bs[0][aCol + 3][m] = rb.w;
    }
    __syncthreads();

    for (int t = 0; t < nt; t++) {
        const int buf = t & 1;
        if (t + 1 < nt) {
            const int k0 = (t + 1) * BKK;
            ra = *(const float4*)&Ag[(long long)aRow * K + k0 + aCol];
            rb = *(const float4*)&Bg[(long long)bRow * K + k0 + aCol];
        }
#pragma unroll
        for (int kk = 0; kk < BKK; kk++) {
            float4 a0 = *(const float4*)&As[buf][kk][ty * 4];
            float4 a1 = *(const float4*)&As[buf][kk][64 + ty * 4];
            float4 b0 = *(const float4*)&Bs[buf][kk][tx * 4];
            float4 b1 = *(const float4*)&Bs[buf][kk][64 + tx * 4];
            float av[8] = {a0.x, a0.y, a0.z, a0.w, a1.x, a1.y, a1.z, a1.w};
            float bv[8] = {b0.x, b0.y, b0.z, b0.w, b1.x, b1.y, b1.z, b1.w};
#pragma unroll
            for (int i = 0; i < 8; i++)
#pragma unroll
                for (int j = 0; j < 8; j++)
                    acc[i][j] += av[i] * bv[j];
        }
        if (t + 1 < nt) {
            const int nb = (t + 1) & 1;
            const int m = tid >> 1;
            As[nb][aCol + 0][m] = ra.x; As[nb][aCol + 1][m] = ra.y;
            As[nb][aCol + 2][m] = ra.z; As[nb][aCol + 3][m] = ra.w;
            Bs[nb][aCol + 0][m] = rb.x; Bs[nb][aCol + 1][m] = rb.y;
            Bs[nb][aCol + 2][m] = rb.z; Bs[nb][aCol + 3][m] = rb.w;
        }
        __syncthreads();
    }

#pragma unroll
    for (int i = 0; i < 8; i++) {
        const int r = row0 + ((i < 4) ? (ty * 4 + i) : (64 + ty * 4 + (i - 4)));
        float4 v0 = make_float4(acc[i][0], acc[i][1], acc[i][2], acc[i][3]);
        float4 v1 = make_float4(acc[i][4], acc[i][5], acc[i][6], acc[i][7]);
        *(float4*)&Cg[(long long)r * N + col0 + tx * 4]      = v0;
        *(float4*)&Cg[(long long)r * N + col0 + 64 + tx * 4] = v1;
    }
}

// ---------------- fp32 -> bf16 hi/lo splits ----------------
__device__ __forceinline__ uint32_t pack2(__nv_bfloat16 a, __nv_bfloat16 b) {
    return (uint32_t)__bfloat16_as_ushort(a) | ((uint32_t)__bfloat16_as_ushort(b) << 16);
}

__global__ __launch_bounds__(256)
void split_kernel(const float* __restrict__ in, __nv_bfloat16* __restrict__ hi,
                  __nv_bfloat16* __restrict__ lo)
{
    const long long i = (long long)blockIdx.x * 256 + threadIdx.x;
    float4 v = ((const float4*)in)[i];
    __nv_bfloat16 h0 = __float2bfloat16(v.x), h1 = __float2bfloat16(v.y);
    __nv_bfloat16 h2 = __float2bfloat16(v.z), h3 = __float2bfloat16(v.w);
    __nv_bfloat16 l0 = __float2bfloat16(v.x - __bfloat162float(h0));
    __nv_bfloat16 l1 = __float2bfloat16(v.y - __bfloat162float(h1));
    __nv_bfloat16 l2 = __float2bfloat16(v.z - __bfloat162float(h2));
    __nv_bfloat16 l3 = __float2bfloat16(v.w - __bfloat162float(h3));
    ((uint2*)hi)[i] = make_uint2(pack2(h0, h1), pack2(h2, h3));
    ((uint2*)lo)[i] = make_uint2(pack2(l0, l1), pack2(l2, l3));
}

// V [4096,256] fp32 -> V^T [256,4096] bf16 hi/lo, 32x32 smem tile transpose
__global__ __launch_bounds__(256)
void vtsplit_kernel(const float* __restrict__ V,
                    __nv_bfloat16* __restrict__ th, __nv_bfloat16* __restrict__ tl)
{
    __shared__ float t[32][33];
    const int x = threadIdx.x & 31;
    const int y = threadIdx.x >> 5;       // 0..7
    const int k0 = blockIdx.x * 32;       // along SK (4096)
    const int n0 = blockIdx.y * 32;       // along DV (256)

#pragma unroll
    for (int i = 0; i < 4; i++)
        t[y + i * 8][x] = V[(long long)(k0 + y + i * 8) * 256 + n0 + x];
    __syncthreads();
#pragma unroll
    for (int i = 0; i < 4; i++) {
        const float v = t[x][y + i * 8];
        const __nv_bfloat16 h = __float2bfloat16(v);
        const long long o = (long long)(n0 + y + i * 8) * 4096 + k0 + x;
        th[o] = h;
        tl[o] = __float2bfloat16(v - __bfloat162float(h));
    }
}

// ---------------- softmax (fp32 in) -> P hi/lo bf16 ----------------
__global__ __launch_bounds__(256)
void softmax_split_kernel(const float* __restrict__ S,
                          __nv_bfloat16* __restrict__ Ph, __nv_bfloat16* __restrict__ Pl)
{
    const long long rbase = (long long)blockIdx.x * 4096;
    const float* p = S + rbase;
    const int tid = threadIdx.x, wid = tid >> 5, lane = tid & 31;

    float4 v[4];
#pragma unroll
    for (int i = 0; i < 4; i++) v[i] = *(const float4*)&p[i * 1024 + tid * 4];

    float m = -INFINITY;
#pragma unroll
    for (int i = 0; i < 4; i++)
        m = fmaxf(m, fmaxf(fmaxf(v[i].x, v[i].y), fmaxf(v[i].z, v[i].w)));
#pragma unroll
    for (int o = 16; o > 0; o >>= 1) m = fmaxf(m, __shfl_xor_sync(0xffffffffu, m, o));

    __shared__ float redm[8], reds[8];
    if (lane == 0) redm[wid] = m;
    __syncthreads();
    m = redm[0];
#pragma unroll
    for (int i = 1; i < 8; i++) m = fmaxf(m, redm[i]);

    float s = 0.f;
#pragma unroll
    for (int i = 0; i < 4; i++) {
        v[i].x = __expf(v[i].x - m); v[i].y = __expf(v[i].y - m);
        v[i].z = __expf(v[i].z - m); v[i].w = __expf(v[i].w - m);
        s += v[i].x + v[i].y + v[i].z + v[i].w;
    }
#pragma unroll
    for (int o = 16; o > 0; o >>= 1) s += __shfl_xor_sync(0xffffffffu, s, o);
    if (lane == 0) reds[wid] = s;
    __syncthreads();
    s = 0.f;
#pragma unroll
    for (int i = 0; i < 8; i++) s += reds[i];
    const float inv = 1.0f / s;

#pragma unroll
    for (int i = 0; i < 4; i++) {
        float f0 = v[i].x * inv, f1 = v[i].y * inv, f2 = v[i].z * inv, f3 = v[i].w * inv;
        __nv_bfloat16 h0 = __float2bfloat16(f0), h1 = __float2bfloat16(f1);
        __nv_bfloat16 h2 = __float2bfloat16(f2), h3 = __float2bfloat16(f3);
        __nv_bfloat16 l0 = __float2bfloat16(f0 - __bfloat162float(h0));
        __nv_bfloat16 l1 = __float2bfloat16(f1 - __bfloat162float(h1));
        __nv_bfloat16 l2 = __float2bfloat16(f2 - __bfloat162float(h2));
        __nv_bfloat16 l3 = __float2bfloat16(f3 - __bfloat162float(h3));
        const long long off = rbase + i * 1024 + tid * 4;
        *(uint2*)&Ph[off] = make_uint2(pack2(h0, h1), pack2(h2, h3));
        *(uint2*)&Pl[off] = make_uint2(pack2(l0, l1), pack2(l2, l3));
    }
}

// ---------------------------------------------------------------------------
extern "C" void kernel_launch(void* const* d_in, const int* in_sizes, int n_in,
                              void* d_out, int out_size)
{
    (void)in_sizes; (void)n_in; (void)out_size;
    const float* X  = (const float*)d_in[0];
    const float* Y  = (const float*)d_in[1];
    const float* Z  = (const float*)d_in[2];
    const float* Wk = (const float*)d_in[3];
    const float* Wv = (const float*)d_in[4];
    float* out = (float*)d_out;

    float *Kp, *Vp, *Sp;
    __nv_bfloat16 *Xh, *Xl, *Kh, *Kl, *Vth, *Vtl, *Ph, *Pl;
    cudaGetSymbolAddress((void**)&Kp,  g_K);
    cudaGetSymbolAddress((void**)&Vp,  g_V);
    cudaGetSymbolAddress((void**)&Sp,  g_S);
    cudaGetSymbolAddress((void**)&Xh,  g_Xh);
    cudaGetSymbolAddress((void**)&Xl,  g_Xl);
    cudaGetSymbolAddress((void**)&Kh,  g_Kh);
    cudaGetSymbolAddress((void**)&Kl,  g_Kl);
    cudaGetSymbolAddress((void**)&Vth, g_Vth);
    cudaGetSymbolAddress((void**)&Vtl, g_Vtl);
    cudaGetSymbolAddress((void**)&Ph,  g_Ph);
    cudaGetSymbolAddress((void**)&Pl,  g_Pl);

    cudaFuncSetAttribute(hmma_gemm_nt, cudaFuncAttributeMaxDynamicSharedMemorySize, SMEMSZ);

    const float rs = 0.0441941738241592f;  // 1/sqrt(512)

    // Projections (fp32 FFMA)
    sgemm_nt<<<dim3(512 / BN, 4096 / BM), 256>>>(Y, Wk, Kp, 512, 512);
    sgemm_nt<<<dim3(256 / BN, 4096 / BM), 256>>>(Z, Wv, Vp, 256, 512);

    // hi/lo splits
    split_kernel<<<(SQB * DDK) / 1024, 256>>>(X, Xh, Xl);
    split_kernel<<<(SKK * DDK) / 1024, 256>>>(Kp, Kh, Kl);
    vtsplit_kernel<<<dim3(SKK / 32, DVV / 32), 256>>>(Vp, Vth, Vtl);

    // S = X K^T * rs  (HMMA 3-split)
    hmma_gemm_nt<<<dim3(SKK / 128, SQB / 128), 256, SMEMSZ>>>(
        Xh, Xl, Kh, Kl, Sp, DDK, SKK, rs);

    // softmax + split P
    softmax_split_kernel<<<SQB, 256>>>(Sp, Ph, Pl);

    // out = P V  (HMMA 3-split)
    hmma_gemm_nt<<<dim3(DVV / 128, SQB / 128), 256, SMEMSZ>>>(
        Ph, Pl, Vth, Vtl, out, SKK, DVV, 1.f);
}

// round 6
// speedup vs baseline: 1.0835x; 1.0835x over previous
#include <cuda_runtime.h>
#include <cuda_bf16.h>
#include <math.h>
#include <stdint.h>

#define SQB 16384
#define SKK 4096
#define DDK 512
#define DVV 256

__device__ __align__(256) float g_K[SKK * DDK];
__device__ __align__(256) float g_V[SKK * DVV];
__device__ __align__(256) float g_S[(long long)SQB * SKK];
__device__ __align__(256) __nv_bfloat16 g_Xh[(long long)SQB * DDK];
__device__ __align__(256) __nv_bfloat16 g_Xl[(long long)SQB * DDK];
__device__ __align__(256) __nv_bfloat16 g_Kh[SKK * DDK];
__device__ __align__(256) __nv_bfloat16 g_Kl[SKK * DDK];
__device__ __align__(256) __nv_bfloat16 g_Vth[DVV * SKK];
__device__ __align__(256) __nv_bfloat16 g_Vtl[DVV * SKK];
__device__ __align__(256) __nv_bfloat16 g_Ph[(long long)SQB * SKK];
__device__ __align__(256) __nv_bfloat16 g_Pl[(long long)SQB * SKK];

// ---------------- helpers ----------------
__device__ __forceinline__ uint32_t smem_u32(const void* p) {
    uint32_t a;
    asm("{ .reg .u64 t; cvta.to.shared.u64 t, %1; cvt.u32.u64 %0, t; }" : "=r"(a) : "l"(p));
    return a;
}
__device__ __forceinline__ void cp16(uint32_t s, const __nv_bfloat16* g) {
    asm volatile("cp.async.cg.shared.global [%0], [%1], 16;"
                 :: "r"(s), "l"(__cvta_generic_to_global(g)) : "memory");
}
#define CP_COMMIT() asm volatile("cp.async.commit_group;" ::: "memory")
#define CP_WAIT(n)  asm volatile("cp.async.wait_group %0;" :: "n"(n) : "memory")

#define LDSM4(r, a) \
    asm volatile("ldmatrix.sync.aligned.m8n8.x4.shared.b16 {%0,%1,%2,%3}, [%4];" \
                 : "=r"((r)[0]), "=r"((r)[1]), "=r"((r)[2]), "=r"((r)[3]) : "r"(a))

#define MMA_BF16(d, a, b) \
    asm volatile("mma.sync.aligned.m16n8k16.row.col.f32.bf16.bf16.f32 " \
                 "{%0,%1,%2,%3}, {%4,%5,%6,%7}, {%8,%9}, {%0,%1,%2,%3};" \
                 : "+f"((d)[0]), "+f"((d)[1]), "+f"((d)[2]), "+f"((d)[3]) \
                 : "r"((a)[0]), "r"((a)[1]), "r"((a)[2]), "r"((a)[3]), \
                   "r"((b)[0]), "r"((b)[1]))

// ---------------- HMMA NT GEMM with bf16 hi/lo 3-MMA split ----------------
// C[M,N] = (Ah+Al)[M,K] * (Bh+Bl)[N,K]^T * scale   (dropping Al*Bl)
// CTA: 128x128 tile, 256 threads (8 warps, each 64x32). K-chunk 32, 2 stages.
// Split terms are iterated OUTERMOST so same-accumulator MMAs are 16 apart.
#define KC 32
#define ROWB 80                 // 64B data + 16B pad per smem row
#define PLANE (128 * ROWB)      // 10240 B
#define OFF_AH 0
#define OFF_AL (1 * PLANE)
#define OFF_BH (2 * PLANE)
#define OFF_BL (3 * PLANE)
#define STAGE  (4 * PLANE)      // 40960 B
#define SMEMSZ (2 * STAGE)      // 81920 B

__device__ __forceinline__ void load_stage(
    uint32_t base, int tid, int kc0, int Kdim,
    const __nv_bfloat16* __restrict__ Ah, const __nv_bfloat16* __restrict__ Al,
    const __nv_bfloat16* __restrict__ Bh, const __nv_bfloat16* __restrict__ Bl,
    long long m0, long long n0)
{
#pragma unroll
    for (int it = 0; it < 2; it++) {
        const int j = tid + it * 256;        // 512 jobs: 128 rows x 4 parts
        const int row = j >> 2;
        const int part = j & 3;
        const uint32_t off = (uint32_t)row * ROWB + part * 16;
        const long long ga = (m0 + row) * (long long)Kdim + kc0 + part * 8;
        const long long gb = (n0 + row) * (long long)Kdim + kc0 + part * 8;
        cp16(base + OFF_AH + off, Ah + ga);
        cp16(base + OFF_AL + off, Al + ga);
        cp16(base + OFF_BH + off, Bh + gb);
        cp16(base + OFF_BL + off, Bl + gb);
    }
    CP_COMMIT();
}

__global__ __launch_bounds__(256)
void hmma_gemm_nt(const __nv_bfloat16* __restrict__ Ah, const __nv_bfloat16* __restrict__ Al,
                  const __nv_bfloat16* __restrict__ Bh, const __nv_bfloat16* __restrict__ Bl,
                  float* __restrict__ C, int Kdim, int ldc, float scale)
{
    extern __shared__ char sm[];
    const uint32_t sb = smem_u32(sm);

    const int tid  = threadIdx.x;
    const int lane = tid & 31;
    const int wid  = tid >> 5;
    const int wm   = wid & 1;    // 2 warps along M
    const int wn   = wid >> 1;   // 4 warps along N
    const long long m0 = (long long)blockIdx.y * 128;
    const long long n0 = (long long)blockIdx.x * 128;

    float acc[4][4][4];
#pragma unroll
    for (int i = 0; i < 4; i++)
#pragma unroll
        for (int j = 0; j < 4; j++)
#pragma unroll
            for (int k = 0; k < 4; k++) acc[i][j][k] = 0.f;

    const int NC = Kdim / KC;

    load_stage(sb,         tid, 0,  Kdim, Ah, Al, Bh, Bl, m0, n0);
    load_stage(sb + STAGE, tid, KC, Kdim, Ah, Al, Bh, Bl, m0, n0);

    const int g = lane >> 3;        // ldmatrix sub-matrix group
    const int r = lane & 7;

    for (int c = 0; c < NC; c++) {
        const int st = c & 1;
        const uint32_t base = sb + st * STAGE;
        if (c + 2 < NC) { CP_WAIT(1); } else { CP_WAIT(0); }
        __syncthreads();

#pragma unroll
        for (int ks = 0; ks < 2; ks++) {
            uint32_t a_h[4][4], a_l[4][4], b_h[4][2], b_l[4][2];
            // A fragments: 4 m16 tiles, hi + lo
#pragma unroll
            for (int mi = 0; mi < 4; mi++) {
                const uint32_t row = wm * 64 + mi * 16 + (g & 1) * 8 + r;
                const uint32_t cb  = ks * 32 + (g >> 1) * 16;
                const uint32_t ad  = base + OFF_AH + row * ROWB + cb;
                LDSM4(a_h[mi], ad);
                LDSM4(a_l[mi], ad + (OFF_AL - OFF_AH));
            }
            // B fragments: 4 n8 tiles loaded as 2 pairs, hi + lo
#pragma unroll
            for (int np = 0; np < 2; np++) {
                const uint32_t row = wn * 32 + np * 16 + (g >> 1) * 8 + r;
                const uint32_t cb  = ks * 32 + (g & 1) * 16;
                const uint32_t bd  = base + OFF_BH + row * ROWB + cb;
                uint32_t t[4];
                LDSM4(t, bd);
                b_h[np * 2][0] = t[0]; b_h[np * 2][1] = t[1];
                b_h[np * 2 + 1][0] = t[2]; b_h[np * 2 + 1][1] = t[3];
                LDSM4(t, bd + (OFF_BL - OFF_BH));
                b_l[np * 2][0] = t[0]; b_l[np * 2][1] = t[1];
                b_l[np * 2 + 1][0] = t[2]; b_l[np * 2 + 1][1] = t[3];
            }
            // 3-term split MMAs, term OUTERMOST: 16 independent MMAs between
            // successive writes to the same accumulator (hides HMMA latency).
#pragma unroll
            for (int mi = 0; mi < 4; mi++)
#pragma unroll
                for (int ni = 0; ni < 4; ni++)
                    MMA_BF16(acc[mi][ni], a_h[mi], b_h[ni]);
#pragma unroll
            for (int mi = 0; mi < 4; mi++)
#pragma unroll
                for (int ni = 0; ni < 4; ni++)
                    MMA_BF16(acc[mi][ni], a_h[mi], b_l[ni]);
#pragma unroll
            for (int mi = 0; mi < 4; mi++)
#pragma unroll
                for (int ni = 0; ni < 4; ni++)
                    MMA_BF16(acc[mi][ni], a_l[mi], b_h[ni]);
        }
        __syncthreads();
        if (c + 2 < NC)
            load_stage(base, tid, (c + 2) * KC, Kdim, Ah, Al, Bh, Bl, m0, n0);
    }

    // epilogue: fragment -> gmem (float2 stores)
#pragma unroll
    for (int mi = 0; mi < 4; mi++)
#pragma unroll
        for (int ni = 0; ni < 4; ni++) {
            const long long row = m0 + wm * 64 + mi * 16 + (lane >> 2);
            const long long col = n0 + wn * 32 + ni * 8 + 2 * (lane & 3);
            float2 v0 = make_float2(acc[mi][ni][0] * scale, acc[mi][ni][1] * scale);
            float2 v1 = make_float2(acc[mi][ni][2] * scale, acc[mi][ni][3] * scale);
            *(float2*)&C[row * ldc + col]       = v0;
            *(float2*)&C[(row + 8) * ldc + col] = v1;
        }
}

// ---------------- fp32 NT SGEMM for projections ----------------
#define BM 128
#define BN 128
#define BKK 8
#define PADW 132

__global__ __launch_bounds__(256, 2)
void sgemm_nt(const float* __restrict__ Ag, const float* __restrict__ Bg,
              float* __restrict__ Cg, int N, int K)
{
    __shared__ float As[2][BKK][PADW];
    __shared__ float Bs[2][BKK][PADW];

    const int tid = threadIdx.x;
    const int tx = tid & 15, ty = tid >> 4;
    const int row0 = blockIdx.y * BM, col0 = blockIdx.x * BN;
    const int aRow = row0 + (tid >> 1);
    const int aCol = (tid & 1) * 4;
    const int bRow = col0 + (tid >> 1);

    float acc[8][8];
#pragma unroll
    for (int i = 0; i < 8; i++)
#pragma unroll
        for (int j = 0; j < 8; j++) acc[i][j] = 0.f;

    const int nt = K / BKK;
    float4 ra = *(const float4*)&Ag[(long long)aRow * K + aCol];
    float4 rb = *(const float4*)&Bg[(long long)bRow * K + aCol];
    {
        const int m = tid >> 1;
        As[0][aCol + 0][m] = ra.x; As[0][aCol + 1][m] = ra.y;
        As[0][aCol + 2][m] = ra.z; As[0][aCol + 3][m] = ra.w;
        Bs[0][aCol + 0][m] = rb.x; Bs[0][aCol + 1][m] = rb.y;
        Bs[0][aCol + 2][m] = rb.z; Bs[0][aCol + 3][m] = rb.w;
    }
    __syncthreads();

    for (int t = 0; t < nt; t++) {
        const int buf = t & 1;
        if (t + 1 < nt) {
            const int k0 = (t + 1) * BKK;
            ra = *(const float4*)&Ag[(long long)aRow * K + k0 + aCol];
            rb = *(const float4*)&Bg[(long long)bRow * K + k0 + aCol];
        }
#pragma unroll
        for (int kk = 0; kk < BKK; kk++) {
            float4 a0 = *(const float4*)&As[buf][kk][ty * 4];
            float4 a1 = *(const float4*)&As[buf][kk][64 + ty * 4];
            float4 b0 = *(const float4*)&Bs[buf][kk][tx * 4];
            float4 b1 = *(const float4*)&Bs[buf][kk][64 + tx * 4];
            float av[8] = {a0.x, a0.y, a0.z, a0.w, a1.x, a1.y, a1.z, a1.w};
            float bv[8] = {b0.x, b0.y, b0.z, b0.w, b1.x, b1.y, b1.z, b1.w};
#pragma unroll
            for (int i = 0; i < 8; i++)
#pragma unroll
                for (int j = 0; j < 8; j++)
                    acc[i][j] += av[i] * bv[j];
        }
        if (t + 1 < nt) {
            const int nb = (t + 1) & 1;
            const int m = tid >> 1;
            As[nb][aCol + 0][m] = ra.x; As[nb][aCol + 1][m] = ra.y;
            As[nb][aCol + 2][m] = ra.z; As[nb][aCol + 3][m] = ra.w;
            Bs[nb][aCol + 0][m] = rb.x; Bs[nb][aCol + 1][m] = rb.y;
            Bs[nb][aCol + 2][m] = rb.z; Bs[nb][aCol + 3][m] = rb.w;
        }
        __syncthreads();
    }

#pragma unroll
    for (int i = 0; i < 8; i++) {
        const int r = row0 + ((i < 4) ? (ty * 4 + i) : (64 + ty * 4 + (i - 4)));
        float4 v0 = make_float4(acc[i][0], acc[i][1], acc[i][2], acc[i][3]);
        float4 v1 = make_float4(acc[i][4], acc[i][5], acc[i][6], acc[i][7]);
        *(float4*)&Cg[(long long)r * N + col0 + tx * 4]      = v0;
        *(float4*)&Cg[(long long)r * N + col0 + 64 + tx * 4] = v1;
    }
}

// ---------------- fp32 -> bf16 hi/lo splits ----------------
__device__ __forceinline__ uint32_t pack2(__nv_bfloat16 a, __nv_bfloat16 b) {
    return (uint32_t)__bfloat16_as_ushort(a) | ((uint32_t)__bfloat16_as_ushort(b) << 16);
}

__global__ __launch_bounds__(256)
void split_kernel(const float* __restrict__ in, __nv_bfloat16* __restrict__ hi,
                  __nv_bfloat16* __restrict__ lo)
{
    const long long i = (long long)blockIdx.x * 256 + threadIdx.x;
    float4 v = ((const float4*)in)[i];
    __nv_bfloat16 h0 = __float2bfloat16(v.x), h1 = __float2bfloat16(v.y);
    __nv_bfloat16 h2 = __float2bfloat16(v.z), h3 = __float2bfloat16(v.w);
    __nv_bfloat16 l0 = __float2bfloat16(v.x - __bfloat162float(h0));
    __nv_bfloat16 l1 = __float2bfloat16(v.y - __bfloat162float(h1));
    __nv_bfloat16 l2 = __float2bfloat16(v.z - __bfloat162float(h2));
    __nv_bfloat16 l3 = __float2bfloat16(v.w - __bfloat162float(h3));
    ((uint2*)hi)[i] = make_uint2(pack2(h0, h1), pack2(h2, h3));
    ((uint2*)lo)[i] = make_uint2(pack2(l0, l1), pack2(l2, l3));
}

// V [4096,256] fp32 -> V^T [256,4096] bf16 hi/lo, 32x32 smem tile transpose
__global__ __launch_bounds__(256)
void vtsplit_kernel(const float* __restrict__ V,
                    __nv_bfloat16* __restrict__ th, __nv_bfloat16* __restrict__ tl)
{
    __shared__ float t[32][33];
    const int x = threadIdx.x & 31;
    const int y = threadIdx.x >> 5;       // 0..7
    const int k0 = blockIdx.x * 32;       // along SK (4096)
    const int n0 = blockIdx.y * 32;       // along DV (256)

#pragma unroll
    for (int i = 0; i < 4; i++)
        t[y + i * 8][x] = V[(long long)(k0 + y + i * 8) * 256 + n0 + x];
    __syncthreads();
#pragma unroll
    for (int i = 0; i < 4; i++) {
        const float v = t[x][y + i * 8];
        const __nv_bfloat16 h = __float2bfloat16(v);
        const long long o = (long long)(n0 + y + i * 8) * 4096 + k0 + x;
        th[o] = h;
        tl[o] = __float2bfloat16(v - __bfloat162float(h));
    }
}

// ---------------- softmax (fp32 in) -> P hi/lo bf16 ----------------
__global__ __launch_bounds__(256)
void softmax_split_kernel(const float* __restrict__ S,
                          __nv_bfloat16* __restrict__ Ph, __nv_bfloat16* __restrict__ Pl)
{
    const long long rbase = (long long)blockIdx.x * 4096;
    const float* p = S + rbase;
    const int tid = threadIdx.x, wid = tid >> 5, lane = tid & 31;

    float4 v[4];
#pragma unroll
    for (int i = 0; i < 4; i++) v[i] = *(const float4*)&p[i * 1024 + tid * 4];

    float m = -INFINITY;
#pragma unroll
    for (int i = 0; i < 4; i++)
        m = fmaxf(m, fmaxf(fmaxf(v[i].x, v[i].y), fmaxf(v[i].z, v[i].w)));
#pragma unroll
    for (int o = 16; o > 0; o >>= 1) m = fmaxf(m, __shfl_xor_sync(0xffffffffu, m, o));

    __shared__ float redm[8], reds[8];
    if (lane == 0) redm[wid] = m;
    __syncthreads();
    m = redm[0];
#pragma unroll
    for (int i = 1; i < 8; i++) m = fmaxf(m, redm[i]);

    float s = 0.f;
#pragma unroll
    for (int i = 0; i < 4; i++) {
        v[i].x = __expf(v[i].x - m); v[i].y = __expf(v[i].y - m);
        v[i].z = __expf(v[i].z - m); v[i].w = __expf(v[i].w - m);
        s += v[i].x + v[i].y + v[i].z + v[i].w;
    }
#pragma unroll
    for (int o = 16; o > 0; o >>= 1) s += __shfl_xor_sync(0xffffffffu, s, o);
    if (lane == 0) reds[wid] = s;
    __syncthreads();
    s = 0.f;
#pragma unroll
    for (int i = 0; i < 8; i++) s += reds[i];
    const float inv = 1.0f / s;

#pragma unroll
    for (int i = 0; i < 4; i++) {
        float f0 = v[i].x * inv, f1 = v[i].y * inv, f2 = v[i].z * inv, f3 = v[i].w * inv;
        __nv_bfloat16 h0 = __float2bfloat16(f0), h1 = __float2bfloat16(f1);
        __nv_bfloat16 h2 = __float2bfloat16(f2), h3 = __float2bfloat16(f3);
        __nv_bfloat16 l0 = __float2bfloat16(f0 - __bfloat162float(h0));
        __nv_bfloat16 l1 = __float2bfloat16(f1 - __bfloat162float(h1));
        __nv_bfloat16 l2 = __float2bfloat16(f2 - __bfloat162float(h2));
        __nv_bfloat16 l3 = __float2bfloat16(f3 - __bfloat162float(h3));
        const long long off = rbase + i * 1024 + tid * 4;
        *(uint2*)&Ph[off] = make_uint2(pack2(h0, h1), pack2(h2, h3));
        *(uint2*)&Pl[off] = make_uint2(pack2(l0, l1), pack2(l2, l3));
    }
}

// ---------------------------------------------------------------------------
extern "C" void kernel_launch(void* const* d_in, const int* in_sizes, int n_in,
                              void* d_out, int out_size)
{
    (void)in_sizes; (void)n_in; (void)out_size;
    const float* X  = (const float*)d_in[0];
    const float* Y  = (const float*)d_in[1];
    const float* Z  = (const float*)d_in[2];
    const float* Wk = (const float*)d_in[3];
    const float* Wv = (const float*)d_in[4];
    float* out = (float*)d_out;

    float *Kp, *Vp, *Sp;
    __nv_bfloat16 *Xh, *Xl, *Kh, *Kl, *Vth, *Vtl, *Ph, *Pl;
    cudaGetSymbolAddress((void**)&Kp,  g_K);
    cudaGetSymbolAddress((void**)&Vp,  g_V);
    cudaGetSymbolAddress((void**)&Sp,  g_S);
    cudaGetSymbolAddress((void**)&Xh,  g_Xh);
    cudaGetSymbolAddress((void**)&Xl,  g_Xl);
    cudaGetSymbolAddress((void**)&Kh,  g_Kh);
    cudaGetSymbolAddress((void**)&Kl,  g_Kl);
    cudaGetSymbolAddress((void**)&Vth, g_Vth);
    cudaGetSymbolAddress((void**)&Vtl, g_Vtl);
    cudaGetSymbolAddress((void**)&Ph,  g_Ph);
    cudaGetSymbolAddress((void**)&Pl,  g_Pl);

    cudaFuncSetAttribute(hmma_gemm_nt, cudaFuncAttributeMaxDynamicSharedMemorySize, SMEMSZ);

    const float rs = 0.0441941738241592f;  // 1/sqrt(512)

    // Projections (fp32 FFMA)
    sgemm_nt<<<dim3(512 / BN, 4096 / BM), 256>>>(Y, Wk, Kp, 512, 512);
    sgemm_nt<<<dim3(256 / BN, 4096 / BM), 256>>>(Z, Wv, Vp, 256, 512);

    // hi/lo splits
    split_kernel<<<(SQB * DDK) / 1024, 256>>>(X, Xh, Xl);
    split_kernel<<<(SKK * DDK) / 1024, 256>>>(Kp, Kh, Kl);
    vtsplit_kernel<<<dim3(SKK / 32, DVV / 32), 256>>>(Vp, Vth, Vtl);

    // S = X K^T * rs  (HMMA 3-split)
    hmma_gemm_nt<<<dim3(SKK / 128, SQB / 128), 256, SMEMSZ>>>(
        Xh, Xl, Kh, Kl, Sp, DDK, SKK, rs);

    // softmax + split P
    softmax_split_kernel<<<SQB, 256>>>(Sp, Ph, Pl);

    // out = P V  (HMMA 3-split)
    hmma_gemm_nt<<<dim3(DVV / 128, SQB / 128), 256, SMEMSZ>>>(
        Ph, Pl, Vth, Vtl, out, SKK, DVV, 1.f);
}